// round 3
// baseline (speedup 1.0000x reference)
#include <cuda_runtime.h>
#include <math.h>

#define N_REG 576
#define IMG   2048
#define H     1024
#define MID   512
#define VOCAB 32000

// ---------------- scratch (device globals; no allocation allowed) -----------
__device__ float g_x1[4096];          // [h2 | vbar | we]
__device__ float g_x2[3072];          // [v | h1n]
__device__ float g_gates[4096];       // reused lstm1 then lstm2
__device__ float g_h1t[MID];
__device__ float g_vt[4][N_REG * MID];  // K-split partials (deterministic, no atomics)
__device__ float g_logits[N_REG];
__device__ float g_a[N_REG];

// ---------------- K1: vbar + embedding gather + x1 build --------------------
__global__ void k_build_x1(const float* __restrict__ V,
                           const float* __restrict__ h2,
                           const float* __restrict__ emb,
                           const int*   __restrict__ w) {
    int j = blockIdx.x * 256 + threadIdx.x;       // 4096 threads
    if (j < 1024) {
        g_x1[j] = h2[j];
    } else if (j < 1024 + IMG) {
        int c = j - 1024;
        float s = 0.f;
        #pragma unroll 8
        for (int r = 0; r < N_REG; r++) s += V[(long)r * IMG + c];
        g_x1[j] = s * (1.0f / N_REG);
    } else {
        g_x1[j] = emb[(long)w[0] * 1024 + (j - 3072)];
    }
}

// ---------------- LSTM gate matvec: warp per output row ---------------------
// gates[j] = dot(W_ih[j,:L], x) + dot(W_hh[j,:1024], h) + b_ih[j] + b_hh[j]
__global__ void k_gates(const float* __restrict__ W_ih,
                        const float* __restrict__ W_hh,
                        const float* __restrict__ b_ih,
                        const float* __restrict__ b_hh,
                        const float* __restrict__ h,
                        int L, int which_x) {
    __shared__ float sx[4096];
    __shared__ float sh[1024];
    int tid = threadIdx.x;
    const float* x = which_x ? g_x2 : g_x1;
    for (int i = tid; i < L; i += 256) sx[i] = x[i];
    for (int i = tid; i < 1024; i += 256) sh[i] = h[i];
    __syncthreads();

    int warp = tid >> 5, lane = tid & 31;
    int j = blockIdx.x * 8 + warp;

    const float4* wr = (const float4*)(W_ih + (long)j * L);
    const float4* xr = (const float4*)sx;
    float acc = 0.f;
    int n4 = L >> 2;
    #pragma unroll 4
    for (int i = lane; i < n4; i += 32) {
        float4 v = wr[i];
        float4 xv = xr[i];
        acc += v.x * xv.x + v.y * xv.y + v.z * xv.z + v.w * xv.w;
    }
    const float4* wh = (const float4*)(W_hh + (long)j * 1024);
    const float4* hr = (const float4*)sh;
    #pragma unroll 4
    for (int i = lane; i < 256; i += 32) {
        float4 v = wh[i];
        float4 hv = hr[i];
        acc += v.x * hv.x + v.y * hv.y + v.z * hv.z + v.w * hv.w;
    }
    #pragma unroll
    for (int o = 16; o > 0; o >>= 1) acc += __shfl_xor_sync(0xffffffffu, acc, o);
    if (lane == 0) g_gates[j] = acc + b_ih[j] + b_hh[j];
}

// ---------------- LSTM cell elementwise -------------------------------------
__global__ void k_cell(const float* __restrict__ c_in,
                       float* __restrict__ h_out,
                       float* __restrict__ c_out) {
    int j = blockIdx.x * 256 + threadIdx.x;       // 1024 threads
    float gi = g_gates[j], gf = g_gates[1024 + j], gg = g_gates[2048 + j], go = g_gates[3072 + j];
    float i = 1.f / (1.f + expf(-gi));
    float f = 1.f / (1.f + expf(-gf));
    float o = 1.f / (1.f + expf(-go));
    float c = f * c_in[j] + i * tanhf(gg);
    c_out[j] = c;
    h_out[j] = o * tanhf(c);
}

// ---------------- h1t = h1n @ lh_w.T + lh_b ---------------------------------
__global__ void k_h1t(const float* __restrict__ lh_w,
                      const float* __restrict__ lh_b,
                      const float* __restrict__ h1n) {
    __shared__ float sh[1024];
    int tid = threadIdx.x;
    for (int i = tid; i < 1024; i += 256) sh[i] = h1n[i];
    __syncthreads();
    int warp = tid >> 5, lane = tid & 31;
    int m = blockIdx.x * 8 + warp;                // 64 blocks
    const float4* wr = (const float4*)(lh_w + (long)m * 1024);
    const float4* hr = (const float4*)sh;
    float acc = 0.f;
    #pragma unroll 4
    for (int i = lane; i < 256; i += 32) {
        float4 v = wr[i];
        float4 hv = hr[i];
        acc += v.x * hv.x + v.y * hv.y + v.z * hv.z + v.w * hv.w;
    }
    #pragma unroll
    for (int o = 16; o > 0; o >>= 1) acc += __shfl_xor_sync(0xffffffffu, acc, o);
    if (lane == 0) g_h1t[m] = acc + lh_b[m];
}

// ---------------- vt GEMM: [576 x 2048] @ [2048 x 512], fp32 tiled ----------
// grid (8 mid-tiles, 9 region-tiles, 4 K-splits), 256 threads, 64x64 tile,
// each thread 4x4 micro-tile. Partials go to g_vt[kz].
__global__ void k_vt(const float* __restrict__ V,
                     const float* __restrict__ lv_w) {
    __shared__ float As[16][68];   // [k][region]
    __shared__ float Bs[16][68];   // [k][mid]
    int tid = threadIdx.x;
    int m0 = blockIdx.x * 64;
    int r0 = blockIdx.y * 64;
    int kbase = blockIdx.z * 512;

    int lr  = tid >> 2;            // 0..63 (row within tile)
    int lk4 = (tid & 3) * 4;       // 0,4,8,12
    int ty  = tid >> 4;            // 0..15
    int tx  = tid & 15;            // 0..15

    float acc[4][4] = {};
    for (int kk = 0; kk < 512; kk += 16) {
        float4 av = *(const float4*)(V    + (long)(r0 + lr) * IMG + kbase + kk + lk4);
        float4 bv = *(const float4*)(lv_w + (long)(m0 + lr) * IMG + kbase + kk + lk4);
        __syncthreads();   // previous iter's readers done before overwrite
        As[lk4 + 0][lr] = av.x; As[lk4 + 1][lr] = av.y;
        As[lk4 + 2][lr] = av.z; As[lk4 + 3][lr] = av.w;
        Bs[lk4 + 0][lr] = bv.x; Bs[lk4 + 1][lr] = bv.y;
        Bs[lk4 + 2][lr] = bv.z; Bs[lk4 + 3][lr] = bv.w;
        __syncthreads();
        #pragma unroll
        for (int k = 0; k < 16; k++) {
            float a[4], b[4];
            #pragma unroll
            for (int i = 0; i < 4; i++) a[i] = As[k][ty * 4 + i];
            #pragma unroll
            for (int j = 0; j < 4; j++) b[j] = Bs[k][tx * 4 + j];
            #pragma unroll
            for (int i = 0; i < 4; i++)
                #pragma unroll
                for (int j = 0; j < 4; j++) acc[i][j] += a[i] * b[j];
        }
    }
    float* outp = g_vt[blockIdx.z];
    #pragma unroll
    for (int i = 0; i < 4; i++)
        #pragma unroll
        for (int j = 0; j < 4; j++)
            outp[(r0 + ty * 4 + i) * MID + m0 + tx * 4 + j] = acc[i][j];
}

// ---------------- attention logits: one block per region --------------------
__global__ void k_logits(const float* __restrict__ lv_b,
                         const float* __restrict__ att_w,
                         const float* __restrict__ att_b) {
    int n = blockIdx.x;
    int tid = threadIdx.x;                         // 128
    const float* __restrict__ p0 = g_vt[0];
    const float* __restrict__ p1 = g_vt[1];
    const float* __restrict__ p2 = g_vt[2];
    const float* __restrict__ p3 = g_vt[3];
    float acc = 0.f;
    for (int m = tid; m < MID; m += 128) {
        int idx = n * MID + m;
        float v = p0[idx] + p1[idx] + p2[idx] + p3[idx] + lv_b[m] + g_h1t[m];
        acc += tanhf(v) * att_w[m];
    }
    __shared__ float red[4];
    #pragma unroll
    for (int o = 16; o > 0; o >>= 1) acc += __shfl_xor_sync(0xffffffffu, acc, o);
    if ((tid & 31) == 0) red[tid >> 5] = acc;
    __syncthreads();
    if (tid == 0) g_logits[n] = red[0] + red[1] + red[2] + red[3] + att_b[0];
}

// ---------------- softmax over 576 regions (single block) -------------------
__global__ void k_softmax() {
    __shared__ float red[8];
    __shared__ float s_max, s_inv;
    int tid = threadIdx.x;                         // 256
    float m = -1e30f;
    for (int n = tid; n < N_REG; n += 256) m = fmaxf(m, g_logits[n]);
    #pragma unroll
    for (int o = 16; o > 0; o >>= 1) m = fmaxf(m, __shfl_xor_sync(0xffffffffu, m, o));
    if ((tid & 31) == 0) red[tid >> 5] = m;
    __syncthreads();
    if (tid == 0) {
        float mm = red[0];
        for (int i = 1; i < 8; i++) mm = fmaxf(mm, red[i]);
        s_max = mm;
    }
    __syncthreads();
    float s = 0.f;
    for (int n = tid; n < N_REG; n += 256) {
        float e = expf(g_logits[n] - s_max);
        g_a[n] = e;
        s += e;
    }
    #pragma unroll
    for (int o = 16; o > 0; o >>= 1) s += __shfl_xor_sync(0xffffffffu, s, o);
    if ((tid & 31) == 0) red[tid >> 5] = s;
    __syncthreads();
    if (tid == 0) {
        float ss = 0.f;
        for (int i = 0; i < 8; i++) ss += red[i];
        s_inv = 1.f / ss;
    }
    __syncthreads();
    for (int n = tid; n < N_REG; n += 256) g_a[n] *= s_inv;
}

// ---------------- weighted pooling + x2 build -------------------------------
__global__ void k_x2(const float* __restrict__ V,
                     const float* __restrict__ h1n) {
    int k = blockIdx.x * 256 + threadIdx.x;        // 3072 threads
    if (k < IMG) {
        float acc = 0.f;
        #pragma unroll 8
        for (int n = 0; n < N_REG; n++) acc += g_a[n] * V[(long)n * IMG + k];
        g_x2[k] = acc;
    } else {
        g_x2[k] = h1n[k - IMG];
    }
}

// ---------------- vocab projection: warp per row ----------------------------
__global__ void k_out(const float* __restrict__ lin_w,
                      const float* __restrict__ lin_b,
                      const float* __restrict__ h2n,
                      float* __restrict__ o) {
    __shared__ float sh[1024];
    int tid = threadIdx.x;
    for (int i = tid; i < 1024; i += 256) sh[i] = h2n[i];
    __syncthreads();
    int warp = tid >> 5, lane = tid & 31;
    int j = blockIdx.x * 8 + warp;                 // 4000 blocks
    const float4* wr = (const float4*)(lin_w + (long)j * 1024);
    const float4* hr = (const float4*)sh;
    float acc = 0.f;
    #pragma unroll 4
    for (int i = lane; i < 256; i += 32) {
        float4 v = wr[i];
        float4 hv = hr[i];
        acc += v.x * hv.x + v.y * hv.y + v.z * hv.z + v.w * hv.w;
    }
    #pragma unroll
    for (int o2 = 16; o2 > 0; o2 >>= 1) acc += __shfl_xor_sync(0xffffffffu, acc, o2);
    if (lane == 0) o[j] = acc + lin_b[j];
}

// ---------------- launch ----------------------------------------------------
extern "C" void kernel_launch(void* const* d_in, const int* in_sizes, int n_in,
                              void* d_out, int out_size) {
    const float* V     = (const float*)d_in[0];
    const int*   w     = (const int*)  d_in[1];
    const float* h1    = (const float*)d_in[2];
    const float* c1    = (const float*)d_in[3];
    const float* h2    = (const float*)d_in[4];
    const float* c2    = (const float*)d_in[5];
    const float* emb   = (const float*)d_in[6];
    const float* W_ih1 = (const float*)d_in[7];
    const float* W_hh1 = (const float*)d_in[8];
    const float* b_ih1 = (const float*)d_in[9];
    const float* b_hh1 = (const float*)d_in[10];
    const float* W_ih2 = (const float*)d_in[11];
    const float* W_hh2 = (const float*)d_in[12];
    const float* b_ih2 = (const float*)d_in[13];
    const float* b_hh2 = (const float*)d_in[14];
    const float* lv_w  = (const float*)d_in[15];
    const float* lv_b  = (const float*)d_in[16];
    const float* lh_w  = (const float*)d_in[17];
    const float* lh_b  = (const float*)d_in[18];
    const float* att_w = (const float*)d_in[19];
    const float* att_b = (const float*)d_in[20];
    const float* lin_w = (const float*)d_in[21];
    const float* lin_b = (const float*)d_in[22];

    float* out = (float*)d_out;
    float* o_p   = out;
    float* h1n_p = out + VOCAB;
    float* c1n_p = out + VOCAB + 1024;
    float* h2n_p = out + VOCAB + 2048;
    float* c2n_p = out + VOCAB + 3072;

    // independent work first (future overlap candidate): attention GEMM
    {
        dim3 g(8, 9, 4);
        k_vt<<<g, 256>>>(V, lv_w);
    }
    // x1 = [h2 | mean(V) | emb[w]]
    k_build_x1<<<16, 256>>>(V, h2, emb, w);
    // LSTM1
    k_gates<<<512, 256>>>(W_ih1, W_hh1, b_ih1, b_hh1, h1, 4096, 0);
    k_cell<<<4, 256>>>(c1, h1n_p, c1n_p);
    // attention
    k_h1t<<<64, 256>>>(lh_w, lh_b, h1n_p);
    k_logits<<<N_REG, 128>>>(lv_b, att_w, att_b);
    k_softmax<<<1, 256>>>();
    k_x2<<<12, 256>>>(V, h1n_p);
    // LSTM2
    k_gates<<<512, 256>>>(W_ih2, W_hh2, b_ih2, b_hh2, h2, 3072, 1);
    k_cell<<<4, 256>>>(c2, h2n_p, c2n_p);
    // vocab projection
    k_out<<<VOCAB / 8, 256>>>(lin_w, lin_b, h2n_p, o_p);
}